// round 1
// baseline (speedup 1.0000x reference)
#include <cuda_runtime.h>
#include <math.h>

// Problem constants (fixed by the dataset)
#define BATCH    2048
#define FID      65536
#define CHUNK    1024              // columns per block (256 threads * float4)
#define NCHUNK   (FID / CHUNK)     // 64
#define ROWS_PB  16                // rows per block in main kernel
#define NROWG    (BATCH / ROWS_PB) // 128
#define WARPS_PB 8                 // 256 threads
#define PARTIALS_PER_ROW (NCHUNK * WARPS_PB)  // 512

// Scratch: 2048 * 512 floats = 4 MB partials + 2048 per-example losses
__device__ float g_partials[BATCH * PARTIALS_PER_ROW];
__device__ float g_exloss[BATCH];

// ---------------------------------------------------------------------------
// Kernel 1: masked dot partials. Bias chunk lives in registers; 16 gate rows
// stream through it. Warp-level reduce only (no block sync in hot path).
// ---------------------------------------------------------------------------
__global__ void __launch_bounds__(256) dot_partials_kernel(
    const float* __restrict__ gate, const float* __restrict__ bias)
{
    const int c    = blockIdx.x;        // column chunk 0..63
    const int g    = blockIdx.y;        // row group 0..127
    const int tid  = threadIdx.x;       // 0..255
    const int warp = tid >> 5;
    const int lane = tid & 31;

    const int col = c * CHUNK + tid * 4;
    const float4 b4 = *reinterpret_cast<const float4*>(bias + col);

    const float* gbase = gate + (size_t)(g * ROWS_PB) * FID + col;

#pragma unroll
    for (int r = 0; r < ROWS_PB; ++r) {
        float4 x = *reinterpret_cast<const float4*>(gbase + (size_t)r * FID);
        float s = x.x * b4.x + x.y * b4.y + x.z * b4.z + x.w * b4.w;
        // warp reduce
        s += __shfl_xor_sync(0xffffffffu, s, 16);
        s += __shfl_xor_sync(0xffffffffu, s, 8);
        s += __shfl_xor_sync(0xffffffffu, s, 4);
        s += __shfl_xor_sync(0xffffffffu, s, 2);
        s += __shfl_xor_sync(0xffffffffu, s, 1);
        if (lane == 0) {
            int row = g * ROWS_PB + r;
            g_partials[(size_t)row * PARTIALS_PER_ROW + c * WARPS_PB + warp] = s;
        }
    }
}

// ---------------------------------------------------------------------------
// Kernel 2: one warp per row — sum 512 partials, emit logits/pred/per-ex loss.
// out layout: [logits(2048), pred(2048), loss(1)]
// ---------------------------------------------------------------------------
__global__ void __launch_bounds__(256) finalize_kernel(
    const float* __restrict__ label, const float* __restrict__ global_bias,
    float* __restrict__ out)
{
    const int warp_in_blk = threadIdx.x >> 5;
    const int lane        = threadIdx.x & 31;
    const int row         = blockIdx.x * 8 + warp_in_blk;
    if (row >= BATCH) return;

    const float* p = g_partials + (size_t)row * PARTIALS_PER_ROW;
    float s = 0.0f;
#pragma unroll
    for (int i = 0; i < PARTIALS_PER_ROW / 32; ++i)
        s += p[i * 32 + lane];

    s += __shfl_xor_sync(0xffffffffu, s, 16);
    s += __shfl_xor_sync(0xffffffffu, s, 8);
    s += __shfl_xor_sync(0xffffffffu, s, 4);
    s += __shfl_xor_sync(0xffffffffu, s, 2);
    s += __shfl_xor_sync(0xffffffffu, s, 1);

    if (lane == 0) {
        float logit = s + global_bias[0];
        out[row]         = logit;
        out[BATCH + row] = 1.0f / (1.0f + __expf(-logit));
        float y = label[row];
        // sigmoid_cross_entropy_with_logits (numerically stable form)
        g_exloss[row] = fmaxf(logit, 0.0f) - logit * y + log1pf(expf(-fabsf(logit)));
    }
}

// ---------------------------------------------------------------------------
// Kernel 3: deterministic single-block reduce of 2048 per-example losses.
// ---------------------------------------------------------------------------
__global__ void __launch_bounds__(1024) loss_reduce_kernel(float* __restrict__ out)
{
    __shared__ float sm[1024];
    const int tid = threadIdx.x;
    float s = g_exloss[tid] + g_exloss[tid + 1024];
    sm[tid] = s;
    __syncthreads();
#pragma unroll
    for (int off = 512; off > 0; off >>= 1) {
        if (tid < off) sm[tid] += sm[tid + off];
        __syncthreads();
    }
    if (tid == 0) out[2 * BATCH] = sm[0];
}

// ---------------------------------------------------------------------------
extern "C" void kernel_launch(void* const* d_in, const int* in_sizes, int n_in,
                              void* d_out, int out_size)
{
    const float* gate        = (const float*)d_in[0]; // [2048, 65536]
    const float* sparse_bias = (const float*)d_in[1]; // [65536]
    const float* global_bias = (const float*)d_in[2]; // [1]
    const float* label       = (const float*)d_in[3]; // [2048]
    float* out = (float*)d_out;                       // [4097]

    dim3 grid1(NCHUNK, NROWG);
    dot_partials_kernel<<<grid1, 256>>>(gate, sparse_bias);
    finalize_kernel<<<BATCH / 8, 256>>>(label, global_bias, out);
    loss_reduce_kernel<<<1, 1024>>>(out);
}

// round 2
// speedup vs baseline: 1.0056x; 1.0056x over previous
#include <cuda_runtime.h>
#include <math.h>

// Problem constants (fixed by the dataset)
#define BATCH    2048
#define FID      65536
#define CHUNK    1024              // columns per block (256 threads * float4)
#define NCHUNK   (FID / CHUNK)     // 64
#define ROWS_PB  16                // rows per block in main kernel
#define NROWG    (BATCH / ROWS_PB) // 128
#define WARPS_PB 8                 // 256 threads

// Scratch: one partial per (row, column-chunk) = 2048*64 floats = 512 KB
__device__ float g_partials[BATCH * NCHUNK];
__device__ float g_exloss[BATCH];

// ---------------------------------------------------------------------------
// Kernel 1: masked dot partials. Two-phase: front-batch all 16 row loads
// (forces MLP_p1 = 16 so DRAM latency is fully covered), then FMA + reduce.
// Block-level smem reduce at the end cuts partials traffic 8x.
// ---------------------------------------------------------------------------
__global__ void __launch_bounds__(256) dot_partials_kernel(
    const float* __restrict__ gate, const float* __restrict__ bias)
{
    const int c    = blockIdx.x;        // column chunk 0..63
    const int g    = blockIdx.y;        // row group 0..127
    const int tid  = threadIdx.x;       // 0..255
    const int warp = tid >> 5;
    const int lane = tid & 31;

    const int col = c * CHUNK + tid * 4;
    const float4 b4 = *reinterpret_cast<const float4*>(bias + col);

    const float* gbase = gate + (size_t)(g * ROWS_PB) * FID + col;

    // Phase 1: issue all 16 LDG.128 back-to-back (max MLP)
    float4 x[ROWS_PB];
#pragma unroll
    for (int r = 0; r < ROWS_PB; ++r)
        x[r] = *reinterpret_cast<const float4*>(gbase + (size_t)r * FID);

    // Phase 2: per-row dot
    float s[ROWS_PB];
#pragma unroll
    for (int r = 0; r < ROWS_PB; ++r)
        s[r] = x[r].x * b4.x + x[r].y * b4.y + x[r].z * b4.z + x[r].w * b4.w;

    // Phase 3: warp reduce each row sum
    __shared__ float sm[ROWS_PB][WARPS_PB];
#pragma unroll
    for (int r = 0; r < ROWS_PB; ++r) {
        float v = s[r];
        v += __shfl_xor_sync(0xffffffffu, v, 16);
        v += __shfl_xor_sync(0xffffffffu, v, 8);
        v += __shfl_xor_sync(0xffffffffu, v, 4);
        v += __shfl_xor_sync(0xffffffffu, v, 2);
        v += __shfl_xor_sync(0xffffffffu, v, 1);
        if (lane == 0) sm[r][warp] = v;
    }
    __syncthreads();

    // Phase 4: one partial per (row, chunk)
    if (tid < ROWS_PB) {
        float t = 0.0f;
#pragma unroll
        for (int w = 0; w < WARPS_PB; ++w) t += sm[tid][w];
        g_partials[(size_t)(g * ROWS_PB + tid) * NCHUNK + c] = t;
    }
}

// ---------------------------------------------------------------------------
// Kernel 2: one warp per row — sum 64 partials, emit logits/pred/per-ex loss.
// out layout: [logits(2048), pred(2048), loss(1)]
// ---------------------------------------------------------------------------
__global__ void __launch_bounds__(256) finalize_kernel(
    const float* __restrict__ label, const float* __restrict__ global_bias,
    float* __restrict__ out)
{
    const int warp_in_blk = threadIdx.x >> 5;
    const int lane        = threadIdx.x & 31;
    const int row         = blockIdx.x * 8 + warp_in_blk;

    const float* p = g_partials + (size_t)row * NCHUNK;
    float s = p[lane] + p[lane + 32];

    s += __shfl_xor_sync(0xffffffffu, s, 16);
    s += __shfl_xor_sync(0xffffffffu, s, 8);
    s += __shfl_xor_sync(0xffffffffu, s, 4);
    s += __shfl_xor_sync(0xffffffffu, s, 2);
    s += __shfl_xor_sync(0xffffffffu, s, 1);

    if (lane == 0) {
        float logit = s + global_bias[0];
        out[row]         = logit;
        out[BATCH + row] = 1.0f / (1.0f + __expf(-logit));
        float y = label[row];
        // sigmoid_cross_entropy_with_logits (numerically stable form)
        g_exloss[row] = fmaxf(logit, 0.0f) - logit * y + log1pf(expf(-fabsf(logit)));
    }
}

// ---------------------------------------------------------------------------
// Kernel 3: deterministic single-block reduce of 2048 per-example losses.
// ---------------------------------------------------------------------------
__global__ void __launch_bounds__(1024) loss_reduce_kernel(float* __restrict__ out)
{
    __shared__ float sm[1024];
    const int tid = threadIdx.x;
    float s = g_exloss[tid] + g_exloss[tid + 1024];
    sm[tid] = s;
    __syncthreads();
#pragma unroll
    for (int off = 512; off > 0; off >>= 1) {
        if (tid < off) sm[tid] += sm[tid + off];
        __syncthreads();
    }
    if (tid == 0) out[2 * BATCH] = sm[0];
}

// ---------------------------------------------------------------------------
extern "C" void kernel_launch(void* const* d_in, const int* in_sizes, int n_in,
                              void* d_out, int out_size)
{
    const float* gate        = (const float*)d_in[0]; // [2048, 65536]
    const float* sparse_bias = (const float*)d_in[1]; // [65536]
    const float* global_bias = (const float*)d_in[2]; // [1]
    const float* label       = (const float*)d_in[3]; // [2048]
    float* out = (float*)d_out;                       // [4097]

    dim3 grid1(NCHUNK, NROWG);
    dot_partials_kernel<<<grid1, 256>>>(gate, sparse_bias);
    finalize_kernel<<<BATCH / 8, 256>>>(label, global_bias, out);
    loss_reduce_kernel<<<1, 1024>>>(out);
}